// round 1
// baseline (speedup 1.0000x reference)
#include <cuda_runtime.h>
#include <cuda_bf16.h>
#include <cstdint>

// Problem constants
#define BATCH   2
#define TSEQ    2048
#define CDIM    1024
#define NHEADS  16
#define HDIM    64          // CDIM / NHEADS
#define QKVN    (3 * CDIM)  // 3072

// Scratch (allocation-free rule: __device__ globals)
__device__ float g_qkv[(size_t)BATCH * TSEQ * 3 * CDIM];  // (B,T,3,H,D) flattened: 48 MB
__device__ float g_att[(size_t)BATCH * TSEQ * CDIM];      // attention out (B,T,C): 16 MB

// ---------------------------------------------------------------------------
// SGEMM:  C[M,N] = A[M,K] @ B[K,N] + bias[N]
// BM=128, BN=128, BK=8, TM=8, TN=8, 256 threads
// ---------------------------------------------------------------------------
__global__ __launch_bounds__(256) void sgemm_bias_kernel(
    const float* __restrict__ A, const float* __restrict__ B,
    const float* __restrict__ bias, float* __restrict__ C,
    int M, int N, int K)
{
    const int BM = 128, BN = 128, BK = 8, TM = 8, TN = 8;
    __shared__ float As[BK][BM];
    __shared__ float Bs[BK][BN];

    const int tid = threadIdx.x;
    const int bm  = blockIdx.y * BM;
    const int bn  = blockIdx.x * BN;

    const int tx = tid % (BN / TN);   // 0..15
    const int ty = tid / (BN / TN);   // 0..15

    // A-tile loader: 128x8 floats = 256 float4; one float4 per thread
    const int arow = tid / 2;             // 0..127
    const int acol = (tid % 2) * 4;       // 0 or 4
    // B-tile loader: 8x128 floats = 256 float4
    const int brow = tid / 32;            // 0..7
    const int bcol = (tid % 32) * 4;      // 0..124

    float acc[TM][TN];
    #pragma unroll
    for (int i = 0; i < TM; i++)
        #pragma unroll
        for (int j = 0; j < TN; j++)
            acc[i][j] = 0.0f;

    for (int k0 = 0; k0 < K; k0 += BK) {
        float4 av = *(const float4*)&A[(size_t)(bm + arow) * K + k0 + acol];
        float4 bv = *(const float4*)&B[(size_t)(k0 + brow) * N + bn + bcol];
        __syncthreads();
        As[acol + 0][arow] = av.x;
        As[acol + 1][arow] = av.y;
        As[acol + 2][arow] = av.z;
        As[acol + 3][arow] = av.w;
        *(float4*)&Bs[brow][bcol] = bv;
        __syncthreads();

        #pragma unroll
        for (int kk = 0; kk < BK; kk++) {
            float ar[TM], br[TN];
            #pragma unroll
            for (int i = 0; i < TM; i++) ar[i] = As[kk][ty * TM + i];
            #pragma unroll
            for (int j = 0; j < TN; j++) br[j] = Bs[kk][tx * TN + j];
            #pragma unroll
            for (int i = 0; i < TM; i++)
                #pragma unroll
                for (int j = 0; j < TN; j++)
                    acc[i][j] += ar[i] * br[j];
        }
    }

    // Epilogue: add bias, store as float4 (8 contiguous cols per thread)
    #pragma unroll
    for (int i = 0; i < TM; i++) {
        const int row = bm + ty * TM + i;
        const int col = bn + tx * TN;
        float out[TN];
        #pragma unroll
        for (int j = 0; j < TN; j++) out[j] = acc[i][j] + bias[col + j];
        *(float4*)&C[(size_t)row * N + col]     = *(float4*)&out[0];
        *(float4*)&C[(size_t)row * N + col + 4] = *(float4*)&out[4];
    }
}

// ---------------------------------------------------------------------------
// Flash attention (fp32). One CTA = one (b, h, 128-query tile).
// 128 threads; thread t owns query row (qt*128 + t): q[64] and acc[64] in regs.
// K/V tiles of 32 keys in shared memory (broadcast reads, conflict-free).
// Online softmax with per-tile max.
// ---------------------------------------------------------------------------
#define KTILE 32

__global__ __launch_bounds__(128) void flash_attn_kernel(
    const float* __restrict__ qkv, float* __restrict__ out)
{
    const int b  = blockIdx.z;
    const int h  = blockIdx.y;
    const int qt = blockIdx.x;
    const int tid = threadIdx.x;
    const int qrow = qt * 128 + tid;

    __shared__ float ks[KTILE][HDIM];
    __shared__ float vs[KTILE][HDIM];
    __shared__ float sbuf[128][KTILE + 1];   // pad: stride 33 -> conflict-free

    // Load q row, pre-scale by D^-0.5
    float q[HDIM];
    {
        const float* qp = qkv + ((size_t)(b * TSEQ + qrow)) * (3 * CDIM) + h * HDIM;
        #pragma unroll
        for (int d = 0; d < HDIM; d += 4) {
            float4 v4 = *(const float4*)&qp[d];
            q[d + 0] = v4.x * 0.125f;
            q[d + 1] = v4.y * 0.125f;
            q[d + 2] = v4.z * 0.125f;
            q[d + 3] = v4.w * 0.125f;
        }
    }

    float m = -1e30f, l = 0.0f;
    float acc[HDIM];
    #pragma unroll
    for (int d = 0; d < HDIM; d++) acc[d] = 0.0f;

    for (int kt = 0; kt < TSEQ; kt += KTILE) {
        __syncthreads();   // previous tile fully consumed
        // Cooperative K/V tile load: 32 rows x 64 floats = 512 float4 per tensor
        // 128 threads -> 4 float4 each per tensor
        for (int i = tid; i < KTILE * (HDIM / 4); i += 128) {
            const int row = i / (HDIM / 4);
            const int c4  = (i % (HDIM / 4)) * 4;
            const size_t base = ((size_t)(b * TSEQ + kt + row)) * (3 * CDIM) + h * HDIM + c4;
            *(float4*)&ks[row][c4] = *(const float4*)&qkv[base + CDIM];       // s=1 (K)
            *(float4*)&vs[row][c4] = *(const float4*)&qkv[base + 2 * CDIM];   // s=2 (V)
        }
        __syncthreads();

        // Pass 1: scores + tile max
        float tmax = -1e30f;
        #pragma unroll 4
        for (int j = 0; j < KTILE; j++) {
            float s = 0.0f;
            #pragma unroll
            for (int d = 0; d < HDIM; d++) s += q[d] * ks[j][d];
            sbuf[tid][j] = s;
            tmax = fmaxf(tmax, s);
        }

        const float mnew = fmaxf(m, tmax);
        const float corr = __expf(m - mnew);
        l *= corr;
        #pragma unroll
        for (int d = 0; d < HDIM; d++) acc[d] *= corr;
        m = mnew;

        // Pass 2: exp + AV accumulate
        for (int j = 0; j < KTILE; j++) {
            const float p = __expf(sbuf[tid][j] - mnew);
            l += p;
            #pragma unroll
            for (int d = 0; d < HDIM; d++) acc[d] += p * vs[j][d];
        }
    }

    const float inv = 1.0f / l;
    float* op = out + ((size_t)(b * TSEQ + qrow)) * CDIM + h * HDIM;
    #pragma unroll
    for (int d = 0; d < HDIM; d += 4) {
        float4 v4;
        v4.x = acc[d + 0] * inv;
        v4.y = acc[d + 1] * inv;
        v4.z = acc[d + 2] * inv;
        v4.w = acc[d + 3] * inv;
        *(float4*)&op[d] = v4;
    }
}

// ---------------------------------------------------------------------------
// Launch
// ---------------------------------------------------------------------------
extern "C" void kernel_launch(void* const* d_in, const int* in_sizes, int n_in,
                              void* d_out, int out_size)
{
    const float* x      = (const float*)d_in[0];  // (B,T,C)
    const float* w_qkv  = (const float*)d_in[1];  // (C, 3C)
    const float* b_qkv  = (const float*)d_in[2];  // (3C)
    const float* w_proj = (const float*)d_in[3];  // (C, C)
    const float* b_proj = (const float*)d_in[4];  // (C)
    float* out = (float*)d_out;                   // (B,T,C)

    float* qkv; cudaGetSymbolAddress((void**)&qkv, g_qkv);
    float* att; cudaGetSymbolAddress((void**)&att, g_att);

    const int M = BATCH * TSEQ;   // 4096

    // 1) QKV projection: (4096,1024) @ (1024,3072) + bias
    {
        dim3 grid(QKVN / 128, M / 128);   // (24, 32)
        sgemm_bias_kernel<<<grid, 256>>>(x, w_qkv, b_qkv, qkv, M, QKVN, CDIM);
    }

    // 2) Flash attention -> g_att (B,T,C)
    {
        dim3 grid(TSEQ / 128, NHEADS, BATCH);   // (16, 16, 2)
        flash_attn_kernel<<<grid, 128>>>(qkv, att);
    }

    // 3) Output projection: (4096,1024) @ (1024,1024) + bias
    {
        dim3 grid(CDIM / 128, M / 128);   // (8, 32)
        sgemm_bias_kernel<<<grid, 256>>>(att, w_proj, b_proj, out, M, CDIM, CDIM);
    }
}

// round 2
// speedup vs baseline: 1.0508x; 1.0508x over previous
#include <cuda_runtime.h>
#include <cuda_bf16.h>
#include <cstdint>

// Problem constants
#define BATCH   2
#define TSEQ    2048
#define CDIM    1024
#define NHEADS  16
#define HDIM    64          // CDIM / NHEADS
#define QKVN    (3 * CDIM)  // 3072

// Scratch (allocation-free rule: __device__ globals)
__device__ float g_qkv[(size_t)BATCH * TSEQ * 3 * CDIM];  // (B,T,3,H,D) flattened: 48 MB
__device__ float g_att[(size_t)BATCH * TSEQ * CDIM];      // attention out (B,T,C): 16 MB

// ---------------------------------------------------------------------------
// SGEMM:  C[M,N] = A[M,K] @ B[K,N] + bias[N]
// BM=128, BN=128, BK=8, TM=8, TN=8, 256 threads
// ---------------------------------------------------------------------------
__global__ __launch_bounds__(256) void sgemm_bias_kernel(
    const float* __restrict__ A, const float* __restrict__ B,
    const float* __restrict__ bias, float* __restrict__ C,
    int M, int N, int K)
{
    const int BM = 128, BN = 128, BK = 8, TM = 8, TN = 8;
    __shared__ float As[BK][BM];
    __shared__ float Bs[BK][BN];

    const int tid = threadIdx.x;
    const int bm  = blockIdx.y * BM;
    const int bn  = blockIdx.x * BN;

    const int tx = tid % (BN / TN);   // 0..15
    const int ty = tid / (BN / TN);   // 0..15

    // A-tile loader: 128x8 floats = 256 float4; one float4 per thread
    const int arow = tid / 2;             // 0..127
    const int acol = (tid % 2) * 4;       // 0 or 4
    // B-tile loader: 8x128 floats = 256 float4
    const int brow = tid / 32;            // 0..7
    const int bcol = (tid % 32) * 4;      // 0..124

    float acc[TM][TN];
    #pragma unroll
    for (int i = 0; i < TM; i++)
        #pragma unroll
        for (int j = 0; j < TN; j++)
            acc[i][j] = 0.0f;

    for (int k0 = 0; k0 < K; k0 += BK) {
        float4 av = *(const float4*)&A[(size_t)(bm + arow) * K + k0 + acol];
        float4 bv = *(const float4*)&B[(size_t)(k0 + brow) * N + bn + bcol];
        __syncthreads();
        As[acol + 0][arow] = av.x;
        As[acol + 1][arow] = av.y;
        As[acol + 2][arow] = av.z;
        As[acol + 3][arow] = av.w;
        *(float4*)&Bs[brow][bcol] = bv;
        __syncthreads();

        #pragma unroll
        for (int kk = 0; kk < BK; kk++) {
            float ar[TM], br[TN];
            #pragma unroll
            for (int i = 0; i < TM; i++) ar[i] = As[kk][ty * TM + i];
            #pragma unroll
            for (int j = 0; j < TN; j++) br[j] = Bs[kk][tx * TN + j];
            #pragma unroll
            for (int i = 0; i < TM; i++)
                #pragma unroll
                for (int j = 0; j < TN; j++)
                    acc[i][j] += ar[i] * br[j];
        }
    }

    // Epilogue: add bias, store as float4 (8 contiguous cols per thread)
    #pragma unroll
    for (int i = 0; i < TM; i++) {
        const int row = bm + ty * TM + i;
        const int col = bn + tx * TN;
        float out[TN];
        #pragma unroll
        for (int j = 0; j < TN; j++) out[j] = acc[i][j] + bias[col + j];
        *(float4*)&C[(size_t)row * N + col]     = *(float4*)&out[0];
        *(float4*)&C[(size_t)row * N + col + 4] = *(float4*)&out[4];
    }
}

// ---------------------------------------------------------------------------
// Flash attention (fp32). One CTA = one (b, h, 128-query tile).
// 128 threads; thread t owns query row (qt*128 + t): q[64] and acc[64] in regs.
// K/V tiles of 32 keys in shared memory (broadcast reads, conflict-free).
// Online softmax with per-tile max.
// ---------------------------------------------------------------------------
#define KTILE 32

__global__ __launch_bounds__(128) void flash_attn_kernel(
    const float* __restrict__ qkv, float* __restrict__ out)
{
    const int b  = blockIdx.z;
    const int h  = blockIdx.y;
    const int qt = blockIdx.x;
    const int tid = threadIdx.x;
    const int qrow = qt * 128 + tid;

    __shared__ float ks[KTILE][HDIM];
    __shared__ float vs[KTILE][HDIM];
    __shared__ float sbuf[128][KTILE + 1];   // pad: stride 33 -> conflict-free

    // Load q row, pre-scale by D^-0.5
    float q[HDIM];
    {
        const float* qp = qkv + ((size_t)(b * TSEQ + qrow)) * (3 * CDIM) + h * HDIM;
        #pragma unroll
        for (int d = 0; d < HDIM; d += 4) {
            float4 v4 = *(const float4*)&qp[d];
            q[d + 0] = v4.x * 0.125f;
            q[d + 1] = v4.y * 0.125f;
            q[d + 2] = v4.z * 0.125f;
            q[d + 3] = v4.w * 0.125f;
        }
    }

    float m = -1e30f, l = 0.0f;
    float acc[HDIM];
    #pragma unroll
    for (int d = 0; d < HDIM; d++) acc[d] = 0.0f;

    for (int kt = 0; kt < TSEQ; kt += KTILE) {
        __syncthreads();   // previous tile fully consumed
        // Cooperative K/V tile load: 32 rows x 64 floats = 512 float4 per tensor
        // 128 threads -> 4 float4 each per tensor
        for (int i = tid; i < KTILE * (HDIM / 4); i += 128) {
            const int row = i / (HDIM / 4);
            const int c4  = (i % (HDIM / 4)) * 4;
            const size_t base = ((size_t)(b * TSEQ + kt + row)) * (3 * CDIM) + h * HDIM + c4;
            *(float4*)&ks[row][c4] = *(const float4*)&qkv[base + CDIM];       // s=1 (K)
            *(float4*)&vs[row][c4] = *(const float4*)&qkv[base + 2 * CDIM];   // s=2 (V)
        }
        __syncthreads();

        // Pass 1: scores + tile max
        float tmax = -1e30f;
        #pragma unroll 4
        for (int j = 0; j < KTILE; j++) {
            float s = 0.0f;
            #pragma unroll
            for (int d = 0; d < HDIM; d++) s += q[d] * ks[j][d];
            sbuf[tid][j] = s;
            tmax = fmaxf(tmax, s);
        }

        const float mnew = fmaxf(m, tmax);
        const float corr = __expf(m - mnew);
        l *= corr;
        #pragma unroll
        for (int d = 0; d < HDIM; d++) acc[d] *= corr;
        m = mnew;

        // Pass 2: exp + AV accumulate
        for (int j = 0; j < KTILE; j++) {
            const float p = __expf(sbuf[tid][j] - mnew);
            l += p;
            #pragma unroll
            for (int d = 0; d < HDIM; d++) acc[d] += p * vs[j][d];
        }
    }

    const float inv = 1.0f / l;
    float* op = out + ((size_t)(b * TSEQ + qrow)) * CDIM + h * HDIM;
    #pragma unroll
    for (int d = 0; d < HDIM; d += 4) {
        float4 v4;
        v4.x = acc[d + 0] * inv;
        v4.y = acc[d + 1] * inv;
        v4.z = acc[d + 2] * inv;
        v4.w = acc[d + 3] * inv;
        *(float4*)&op[d] = v4;
    }
}

// ---------------------------------------------------------------------------
// Launch
// ---------------------------------------------------------------------------
extern "C" void kernel_launch(void* const* d_in, const int* in_sizes, int n_in,
                              void* d_out, int out_size)
{
    const float* x      = (const float*)d_in[0];  // (B,T,C)
    const float* w_qkv  = (const float*)d_in[1];  // (C, 3C)
    const float* b_qkv  = (const float*)d_in[2];  // (3C)
    const float* w_proj = (const float*)d_in[3];  // (C, C)
    const float* b_proj = (const float*)d_in[4];  // (C)
    float* out = (float*)d_out;                   // (B,T,C)

    float* qkv; cudaGetSymbolAddress((void**)&qkv, g_qkv);
    float* att; cudaGetSymbolAddress((void**)&att, g_att);

    const int M = BATCH * TSEQ;   // 4096

    // 1) QKV projection: (4096,1024) @ (1024,3072) + bias
    {
        dim3 grid(QKVN / 128, M / 128);   // (24, 32)
        sgemm_bias_kernel<<<grid, 256>>>(x, w_qkv, b_qkv, qkv, M, QKVN, CDIM);
    }

    // 2) Flash attention -> g_att (B,T,C)
    {
        dim3 grid(TSEQ / 128, NHEADS, BATCH);   // (16, 16, 2)
        flash_attn_kernel<<<grid, 128>>>(qkv, att);
    }

    // 3) Output projection: (4096,1024) @ (1024,1024) + bias
    {
        dim3 grid(CDIM / 128, M / 128);   // (8, 32)
        sgemm_bias_kernel<<<grid, 256>>>(att, w_proj, b_proj, out, M, CDIM, CDIM);
    }
}